// round 15
// baseline (speedup 1.0000x reference)
#include <cuda_runtime.h>
#include <cuda_fp16.h>
#include <mma.h>
#include <math.h>

using namespace nvcuda;

// Problem constants
#define WE   300      // word embedding dim
#define WE2  320      // padded (fp16 staging) word dim
#define WEP  320      // padded gNT stride (mult of 32 for k-chunking)
#define KC   32       // GEMM k-chunk
#define DEm  256      // doc embedding dim
#define NV   50000    // vocab
#define NDn  100000   // num docs
#define NB   4096     // batch
#define NGw  10       // words per bag
#define NZ   10       // negatives
#define NENT (NB * 11)      // 45056 (b, slot) -> doc entries
#define NBKT (NDn / 32)     // 3125 doc buckets (32 cols each)
#define REG_BLOCKS 2048

// ---------------- scratch (device globals; no allocation) ----------------
__device__ __align__(16) __half g_rvT16[(size_t)NV * WE2];  // 32 MB fp16 staging
__device__ __align__(16) float g_gNT[NB * WEP];             // 4096 x 320 (pad=0)
__device__ __align__(16) float g_Ct[NB * DEm];              // t_pre^T: 4096 x 256
__device__ int   g_bcnt[NBKT];
__device__ int   g_boff[NBKT + 1];
__device__ int   g_bcur[NBKT];
__device__ int   g_bent[NENT];
__device__ float g_dots[NENT];
__device__ float g_sum [DEm];      // atomic stats accumulators
__device__ float g_ssum[DEm];
__device__ float g_lpw[NB];
__device__ float g_regpart[REG_BLOCKS];

__device__ __forceinline__ float warpSum(float v) {
#pragma unroll
    for (int o = 16; o; o >>= 1) v += __shfl_down_sync(0xffffffffu, v, o);
    return v;
}
__device__ __forceinline__ float log_sig(float x) {
    return (x >= 0.f) ? -log1pf(expf(-x)) : x - log1pf(expf(x));
}

// ================= CSR bucket build (side stream; ids only) ================
__global__ void __launch_bounds__(256) k_bzero() {
    int i = blockIdx.x * 256 + threadIdx.x;
    if (i < NBKT) g_bcnt[i] = 0;
}
__global__ void __launch_bounds__(256)
k_bcount(const int* __restrict__ doc_ids, const int* __restrict__ neg_ids) {
    int i = blockIdx.x * 256 + threadIdx.x;
    if (i >= NENT) return;
    int doc = (i < NB) ? doc_ids[i] : neg_ids[i - NB];
    atomicAdd(&g_bcnt[doc >> 5], 1);
}
__global__ void __launch_bounds__(1024) k_bscan() {
    const int T = 1024, CH = (NBKT + T - 1) / T;   // 4
    __shared__ int s[T];
    int t = threadIdx.x;
    int base = t * CH;
    int sum = 0;
#pragma unroll 1
    for (int i = 0; i < CH; i++) {
        int v = base + i;
        if (v < NBKT) sum += g_bcnt[v];
    }
    s[t] = sum;
    __syncthreads();
    for (int o = 1; o < T; o <<= 1) {
        int x = (t >= o) ? s[t - o] : 0;
        __syncthreads();
        s[t] += x;
        __syncthreads();
    }
    int run = s[t] - sum;
#pragma unroll 1
    for (int i = 0; i < CH; i++) {
        int v = base + i;
        if (v < NBKT) {
            g_boff[v] = run;
            g_bcur[v] = run;
            run += g_bcnt[v];
        }
    }
    if (t == T - 1) g_boff[NBKT] = s[T - 1];
}
__global__ void __launch_bounds__(256)
k_bfill(const int* __restrict__ doc_ids, const int* __restrict__ neg_ids) {
    int i = blockIdx.x * 256 + threadIdx.x;
    if (i >= NENT) return;
    int b, v, doc;
    if (i < NB) { b = i; v = 0; doc = doc_ids[i]; }
    else {
        int j = i - NB;
        b = j / NZ; v = 1 + (j % NZ); doc = neg_ids[j];
    }
    int pos = atomicAdd(&g_bcur[doc >> 5], 1);
    g_bent[pos] = ((doc & 31) << 16) | (b * 11 + v);
}

// Side stream: grid-stride sum(rd^2) — streams rd once, warms L2 for k_dots.
__global__ void __launch_bounds__(256) k_reg(const float* __restrict__ rd) {
    const float4* r4 = (const float4*)rd;
    const int n4 = DEm * NDn / 4;     // 6,400,000
    float s = 0.f;
    for (int i = blockIdx.x * blockDim.x + threadIdx.x; i < n4;
         i += gridDim.x * blockDim.x) {
        float4 v = __ldg(&r4[i]);
        s += v.x * v.x + v.y * v.y + v.z * v.z + v.w * v.w;
    }
    s = warpSum(s);
    __shared__ float red[8];
    if ((threadIdx.x & 31) == 0) red[threadIdx.x >> 5] = s;
    __syncthreads();
    if (threadIdx.x == 0) {
        float t = 0.f;
#pragma unroll
        for (int i = 0; i < 8; i++) t += red[i];
        g_regpart[blockIdx.x] = t;
    }
}

// ================= main chain ==============================================
// K1: transpose rv (300 x 50000) -> fp16 rvT16 (50000 x 320, zero-padded).
__global__ void __launch_bounds__(256) k_trv(const float* __restrict__ rv) {
    __shared__ float t[64][33];
    int x0 = blockIdx.x * 32;      // v base
    int y0 = blockIdx.y * 64;      // k base
    int tx = threadIdx.x & 31, ty = threadIdx.x >> 5;   // 32 x 8
#pragma unroll
    for (int j = 0; j < 64; j += 8) {
        int k = y0 + ty + j, v = x0 + tx;
        t[ty + j][tx] = (k < WE && v < NV) ? rv[(size_t)k * NV + v] : 0.f;
    }
    __syncthreads();
#pragma unroll
    for (int j = 0; j < 32; j += 8) {
        int v = x0 + ty + j;
        if (v < NV) {
            __half2 h = __halves2half2(__float2half(t[2 * tx][ty + j]),
                                       __float2half(t[2 * tx + 1][ty + j]));
            *(__half2*)&g_rvT16[(size_t)v * WE2 + y0 + 2 * tx] = h;
        }
    }
}

// K2: gather 10 word rows (half2), mean, L2-normalize. Blocks 0/1 zero the
// stats accumulators. Writes gNT rows padded to WEP=320 (k>=300 exact 0).
__global__ void __launch_bounds__(256) k_gather(const int* __restrict__ word_ids) {
    int b = blockIdx.x;
    int tid = threadIdx.x;
    if (b == 0 && tid < DEm) g_sum[tid]  = 0.f;
    if (b == 1 && tid < DEm) g_ssum[tid] = 0.f;
    __shared__ int   wid[NGw];
    __shared__ float red[8];
    __shared__ float rinv;
    if (tid < NGw) wid[tid] = word_ids[b * NGw + tid];
    __syncthreads();
    float gx = 0.f, gy = 0.f;
    if (tid < 160) {
#pragma unroll
        for (int j = 0; j < NGw; j++) {
            __half2 h = *(const __half2*)&g_rvT16[(size_t)wid[j] * WE2 + 2 * tid];
            float2 f = __half22float2(h);
            gx += f.x; gy += f.y;
        }
        gx *= 0.1f; gy *= 0.1f;
    }
    float s = warpSum(gx * gx + gy * gy);
    if ((tid & 31) == 0) red[tid >> 5] = s;
    __syncthreads();
    if (tid == 0) {
        float t = 0.f;
#pragma unroll
        for (int i = 0; i < 8; i++) t += red[i];
        rinv = rsqrtf(t);
    }
    __syncthreads();
    if (tid < 160)   // covers k 0..319; k>=300 are 0 (rvT16 pad)
        *(float2*)&g_gNT[b * WEP + 2 * tid] = make_float2(gx * rinv, gy * rinv);
}

// K3: tf32 tensor-core GEMM with SMEM-staged tiles (R14, unchanged).
__global__ void __launch_bounds__(512) k_gemm(const float* __restrict__ proj) {
    __shared__ float As[64][36];    // [n][k] chunk
    __shared__ float Bs[64][36];    // [m][k] chunk == B(k,m) col-major
    int tid  = threadIdx.x;
    int warp = tid >> 5;
    int wn = warp >> 2, wm = warp & 3;
    int n0 = blockIdx.x * 64, m0 = blockIdx.y * 64;

    wmma::fragment<wmma::accumulator, 16, 16, 8, float> c;
    wmma::fill_fragment(c, 0.f);

#pragma unroll 1
    for (int k0 = 0; k0 < WEP; k0 += KC) {      // 10 chunks
        {
            int row = tid >> 3, q = tid & 7;
            *(float4*)&As[row][q * 4] =
                *(const float4*)&g_gNT[(n0 + row) * WEP + k0 + q * 4];
        }
        {
#pragma unroll
            for (int i = tid; i < 64 * KC; i += 512) {
                int m = i >> 5, k = i & 31;
                int kk = k0 + k;
                Bs[m][k] = (kk < WE) ? proj[(size_t)(m0 + m) * WE + kk] : 0.f;
            }
        }
        __syncthreads();
#pragma unroll
        for (int kk = 0; kk < KC; kk += 8) {
            wmma::fragment<wmma::matrix_a, 16, 16, 8, wmma::precision::tf32,
                           wmma::row_major> a;
            wmma::fragment<wmma::matrix_b, 16, 16, 8, wmma::precision::tf32,
                           wmma::col_major> b;
            wmma::load_matrix_sync(a, &As[wn * 16][kk], 36);
            wmma::load_matrix_sync(b, &Bs[wm * 16][kk], 36);
#pragma unroll
            for (int i = 0; i < a.num_elements; i++)
                a.x[i] = wmma::__float_to_tf32(a.x[i]);
#pragma unroll
            for (int i = 0; i < b.num_elements; i++)
                b.x[i] = wmma::__float_to_tf32(b.x[i]);
            wmma::mma_sync(c, a, b, c);
        }
        __syncthreads();
    }
    wmma::store_matrix_sync(&g_Ct[(n0 + wn * 16) * DEm + m0 + wm * 16], c,
                            DEm, wmma::mem_row_major);
    __syncthreads();

    // fused stats: per-m partial sum/sumsq over this block's 64 n values
    __shared__ float sS[4][64];
    __shared__ float sQ[4][64];
    float s = 0.f, q = 0.f;
    int ml = tid & 63, grp = (tid >> 6) & 3;
    if (tid < 256) {
#pragma unroll
        for (int i = 0; i < 16; i++) {
            float x = g_Ct[(n0 + grp * 16 + i) * DEm + m0 + ml];
            s += x; q += x * x;
        }
        sS[grp][ml] = s;
        sQ[grp][ml] = q;
    }
    __syncthreads();
    if (tid < 64) {
        float ts = 0.f, tq = 0.f;
#pragma unroll
        for (int g2 = 0; g2 < 4; g2++) { ts += sS[g2][tid]; tq += sQ[g2][tid]; }
        atomicAdd(&g_sum [m0 + tid], ts);
        atomicAdd(&g_ssum[m0 + tid], tq);
    }
}

// K4: bucketed dots — rd tiles now come from L2 (warmed by k_reg); inline
// batchnorm from atomic stats; all dot-products for this bucket's entries.
__global__ void __launch_bounds__(256)
k_dots(const float* __restrict__ rd, const float* __restrict__ beta) {
    __shared__ float tile[DEm][33];     // [d][c], conflict-free both phases
    __shared__ float sMean[DEm], sFac[DEm], sBeta[DEm];
    int c0 = blockIdx.x * 32;
    int tx = threadIdx.x & 31;
    int ty = threadIdx.x >> 5;          // warp id 0..7
#pragma unroll
    for (int d0 = 0; d0 < DEm; d0 += 8) {
        tile[d0 + ty][tx] = __ldg(&rd[(size_t)(d0 + ty) * NDn + c0 + tx]);
    }
    {
        int d = threadIdx.x;
        float s = g_sum[d], q = g_ssum[d];
        float mean = s * (1.0f / NB);
        float var  = fmaxf((q - (float)NB * mean * mean) * (1.0f / (NB - 1)), 0.f);
        sMean[d] = mean;
        sFac[d]  = rsqrtf(sqrtf(var));   // 1/sqrt(std), std ddof=1
        sBeta[d] = beta[d];
    }
    __syncthreads();
    int o0 = g_boff[blockIdx.x];
    int o1 = g_boff[blockIdx.x + 1];
    for (int e = o0 + ty; e < o1; e += 8) {
        int ent = g_bent[e];
        int c   = ent >> 16;
        int idx = ent & 0xFFFF;         // b*11 + v
        int b   = idx / 11;
        const float* crow = &g_Ct[b * DEm];
        float acc = 0.f;
#pragma unroll
        for (int i = 0; i < 8; i++) {
            int d = tx + i * 32;
            float tv = fminf(fmaxf((crow[d] - sMean[d]) * sFac[d] + sBeta[d],
                                   -1.f), 1.f);
            acc += tv * tile[d][c];
        }
        acc = warpSum(acc);
        if (tx == 0) g_dots[idx] = acc;
    }
}

// K5: per-batch loss from 11 dots
__global__ void __launch_bounds__(128) k_loss() {
    int b = blockIdx.x * 128 + threadIdx.x;     // 32 blocks x 128
    const float* d = &g_dots[b * 11];
    float lp = 10.f * fminf(log_sig(d[0]), -1.0005003e-3f);   // log(0.999)
    float ns = 0.f;
#pragma unroll
    for (int z = 0; z < NZ; z++)
        ns += fmaxf(log_sig(-d[1 + z]), -4.60517019f);        // log(0.01)
    g_lpw[b] = 0.55f * (lp + ns);                             // (Z+1)/(2Z)
}

// K6: final reduce (double) + sum(proj^2) inline
__global__ void __launch_bounds__(256)
k_final(const float* __restrict__ proj, float* __restrict__ out) {
    int t = threadIdx.x;
    double a = 0.0, r = 0.0;
    for (int i = t; i < NB;         i += 256) a += (double)g_lpw[i];
    for (int i = t; i < REG_BLOCKS; i += 256) r += (double)g_regpart[i];
    {
        float ps = 0.f;
        for (int i = t; i < WE * DEm; i += 256) {
            float v = proj[i];
            ps += v * v;
        }
        r += (double)ps;
    }
    __shared__ double sa[256], sr[256];
    sa[t] = a; sr[t] = r;
    __syncthreads();
    for (int o = 128; o; o >>= 1) {
        if (t < o) { sa[t] += sa[t + o]; sr[t] += sr[t + o]; }
        __syncthreads();
    }
    if (t == 0)
        out[0] = (float)(sa[0] / (double)NB + (0.01 / (2.0 * NB)) * sr[0]);
}

// ---------------------------------------------------------------------------
static cudaStream_t g_s2;
static cudaEvent_t  g_e1, g_e2;
namespace {
struct _Init {
    _Init() {
        cudaStreamCreateWithFlags(&g_s2, cudaStreamNonBlocking);
        cudaEventCreateWithFlags(&g_e1, cudaEventDisableTiming);
        cudaEventCreateWithFlags(&g_e2, cudaEventDisableTiming);
    }
} _init;
}

extern "C" void kernel_launch(void* const* d_in, const int* in_sizes, int n_in,
                              void* d_out, int out_size) {
    const float* rv       = (const float*)d_in[0];
    const float* rd       = (const float*)d_in[1];
    const float* proj     = (const float*)d_in[2];
    const float* beta     = (const float*)d_in[3];
    const int*   word_ids = (const int*)d_in[4];
    const int*   doc_ids  = (const int*)d_in[5];
    const int*   neg_ids  = (const int*)d_in[6];

    // Side stream: CSR bucket build, then rd stream (sum(rd^2) + L2 warm),
    // overlapped with trv -> gather -> gemm on the main stream.
    cudaEventRecord(g_e1, 0);
    cudaStreamWaitEvent(g_s2, g_e1, 0);
    k_bzero <<<(NBKT + 255) / 256, 256, 0, g_s2>>>();
    k_bcount<<<(NENT + 255) / 256, 256, 0, g_s2>>>(doc_ids, neg_ids);
    k_bscan <<<1, 1024, 0, g_s2>>>();
    k_bfill <<<(NENT + 255) / 256, 256, 0, g_s2>>>(doc_ids, neg_ids);
    k_reg   <<<REG_BLOCKS, 256, 0, g_s2>>>(rd);
    cudaEventRecord(g_e2, g_s2);

    // Main chain
    k_trv   <<<dim3((NV + 31) / 32, WE2 / 64), 256>>>(rv);
    k_gather<<<NB, 256>>>(word_ids);
    k_gemm  <<<dim3(NB / 64, DEm / 64), 512>>>(proj);
    cudaStreamWaitEvent(0, g_e2, 0);   // join: dots need buckets + warm rd
    k_dots  <<<NBKT, 256>>>(rd, beta);
    k_loss  <<<NB / 128, 128>>>();
    k_final <<<1, 256>>>(proj, (float*)d_out);
}

// round 16
// speedup vs baseline: 1.2543x; 1.2543x over previous
#include <cuda_runtime.h>
#include <cuda_fp16.h>
#include <mma.h>
#include <math.h>

using namespace nvcuda;

// Problem constants
#define WE   300      // word embedding dim
#define WE2  320      // padded (fp16 staging) word dim
#define WEP  320      // padded gNT stride (mult of 32 for k-chunking)
#define KC   32       // GEMM k-chunk
#define DEm  256      // doc embedding dim
#define NV   50000    // vocab
#define NDn  100000   // num docs
#define NB   4096     // batch
#define NGw  10       // words per bag
#define NZ   10       // negatives
#define NENT (NB * 11)      // 45056 (b, slot) -> doc entries
#define NBKT (NDn / 32)     // 3125 doc buckets (32 cols each)
#define TAILB 32            // k_tail blocks
#define RSLICE ((NBKT + TAILB - 1) / TAILB)     // 98
#define PSLICE ((WE * DEm) / TAILB)             // 2400

// ---------------- scratch (device globals; no allocation) ----------------
__device__ __align__(16) __half g_rvT16[(size_t)NV * WE2];  // 32 MB fp16 staging
__device__ __align__(16) float g_gNT[NB * WEP];             // 4096 x 320 (pad=0)
__device__ __align__(16) float g_Ct[NB * DEm];              // t_pre^T: 4096 x 256
__device__ int   g_bcnt[NBKT];
__device__ int   g_boff[NBKT + 1];
__device__ int   g_bcur[NBKT];
__device__ int   g_bent[NENT];
__device__ float g_dots[NENT];
__device__ float g_sum [DEm];      // atomic stats accumulators
__device__ float g_ssum[DEm];
__device__ float g_regpart[NBKT];
__device__ double g_accA;          // loss accumulator (double atomics)
__device__ double g_accR;          // regularizer accumulator
__device__ int    g_ticket;

__device__ __forceinline__ float warpSum(float v) {
#pragma unroll
    for (int o = 16; o; o >>= 1) v += __shfl_down_sync(0xffffffffu, v, o);
    return v;
}
__device__ __forceinline__ float log_sig(float x) {
    return (x >= 0.f) ? -log1pf(expf(-x)) : x - log1pf(expf(x));
}

// ================= CSR bucket build (side stream; ids only) ================
__global__ void __launch_bounds__(256) k_bzero() {
    int i = blockIdx.x * 256 + threadIdx.x;
    if (i < NBKT) g_bcnt[i] = 0;
}
__global__ void __launch_bounds__(256)
k_bcount(const int* __restrict__ doc_ids, const int* __restrict__ neg_ids) {
    int i = blockIdx.x * 256 + threadIdx.x;
    if (i >= NENT) return;
    int doc = (i < NB) ? doc_ids[i] : neg_ids[i - NB];
    atomicAdd(&g_bcnt[doc >> 5], 1);
}
__global__ void __launch_bounds__(1024) k_bscan() {
    const int T = 1024, CH = (NBKT + T - 1) / T;   // 4
    __shared__ int s[T];
    int t = threadIdx.x;
    int base = t * CH;
    int sum = 0;
#pragma unroll 1
    for (int i = 0; i < CH; i++) {
        int v = base + i;
        if (v < NBKT) sum += g_bcnt[v];
    }
    s[t] = sum;
    __syncthreads();
    for (int o = 1; o < T; o <<= 1) {
        int x = (t >= o) ? s[t - o] : 0;
        __syncthreads();
        s[t] += x;
        __syncthreads();
    }
    int run = s[t] - sum;
#pragma unroll 1
    for (int i = 0; i < CH; i++) {
        int v = base + i;
        if (v < NBKT) {
            g_boff[v] = run;
            g_bcur[v] = run;
            run += g_bcnt[v];
        }
    }
    if (t == T - 1) g_boff[NBKT] = s[T - 1];
}
__global__ void __launch_bounds__(256)
k_bfill(const int* __restrict__ doc_ids, const int* __restrict__ neg_ids) {
    int i = blockIdx.x * 256 + threadIdx.x;
    if (i >= NENT) return;
    int b, v, doc;
    if (i < NB) { b = i; v = 0; doc = doc_ids[i]; }
    else {
        int j = i - NB;
        b = j / NZ; v = 1 + (j % NZ); doc = neg_ids[j];
    }
    int pos = atomicAdd(&g_bcur[doc >> 5], 1);
    g_bent[pos] = ((doc & 31) << 16) | (b * 11 + v);
}

// ================= main chain ==============================================
// K1: transpose rv (300 x 50000) -> fp16 rvT16 (50000 x 320, zero-padded).
__global__ void __launch_bounds__(256) k_trv(const float* __restrict__ rv) {
    __shared__ float t[64][33];
    int x0 = blockIdx.x * 32;      // v base
    int y0 = blockIdx.y * 64;      // k base
    int tx = threadIdx.x & 31, ty = threadIdx.x >> 5;   // 32 x 8
#pragma unroll
    for (int j = 0; j < 64; j += 8) {
        int k = y0 + ty + j, v = x0 + tx;
        t[ty + j][tx] = (k < WE && v < NV) ? rv[(size_t)k * NV + v] : 0.f;
    }
    __syncthreads();
#pragma unroll
    for (int j = 0; j < 32; j += 8) {
        int v = x0 + ty + j;
        if (v < NV) {
            __half2 h = __halves2half2(__float2half(t[2 * tx][ty + j]),
                                       __float2half(t[2 * tx + 1][ty + j]));
            *(__half2*)&g_rvT16[(size_t)v * WE2 + y0 + 2 * tx] = h;
        }
    }
}

// K2: gather 10 word rows (half2), mean, L2-normalize. Blocks 0/1 zero the
// stats accumulators; block 2 zeros the tail accumulators/ticket.
__global__ void __launch_bounds__(256) k_gather(const int* __restrict__ word_ids) {
    int b = blockIdx.x;
    int tid = threadIdx.x;
    if (b == 0 && tid < DEm) g_sum[tid]  = 0.f;
    if (b == 1 && tid < DEm) g_ssum[tid] = 0.f;
    if (b == 2 && tid == 0) { g_accA = 0.0; g_accR = 0.0; g_ticket = 0; }
    __shared__ int   wid[NGw];
    __shared__ float red[8];
    __shared__ float rinv;
    if (tid < NGw) wid[tid] = word_ids[b * NGw + tid];
    __syncthreads();
    float gx = 0.f, gy = 0.f;
    if (tid < 160) {
#pragma unroll
        for (int j = 0; j < NGw; j++) {
            __half2 h = *(const __half2*)&g_rvT16[(size_t)wid[j] * WE2 + 2 * tid];
            float2 f = __half22float2(h);
            gx += f.x; gy += f.y;
        }
        gx *= 0.1f; gy *= 0.1f;
    }
    float s = warpSum(gx * gx + gy * gy);
    if ((tid & 31) == 0) red[tid >> 5] = s;
    __syncthreads();
    if (tid == 0) {
        float t = 0.f;
#pragma unroll
        for (int i = 0; i < 8; i++) t += red[i];
        rinv = rsqrtf(t);
    }
    __syncthreads();
    if (tid < 160)   // covers k 0..319; k>=300 are 0 (rvT16 pad)
        *(float2*)&g_gNT[b * WEP + 2 * tid] = make_float2(gx * rinv, gy * rinv);
}

// K3: tf32 tensor-core GEMM with SMEM-staged tiles (R14, unchanged).
__global__ void __launch_bounds__(512) k_gemm(const float* __restrict__ proj) {
    __shared__ float As[64][36];    // [n][k] chunk
    __shared__ float Bs[64][36];    // [m][k] chunk == B(k,m) col-major
    int tid  = threadIdx.x;
    int warp = tid >> 5;
    int wn = warp >> 2, wm = warp & 3;
    int n0 = blockIdx.x * 64, m0 = blockIdx.y * 64;

    wmma::fragment<wmma::accumulator, 16, 16, 8, float> c;
    wmma::fill_fragment(c, 0.f);

#pragma unroll 1
    for (int k0 = 0; k0 < WEP; k0 += KC) {      // 10 chunks
        {
            int row = tid >> 3, q = tid & 7;
            *(float4*)&As[row][q * 4] =
                *(const float4*)&g_gNT[(n0 + row) * WEP + k0 + q * 4];
        }
        {
#pragma unroll
            for (int i = tid; i < 64 * KC; i += 512) {
                int m = i >> 5, k = i & 31;
                int kk = k0 + k;
                Bs[m][k] = (kk < WE) ? proj[(size_t)(m0 + m) * WE + kk] : 0.f;
            }
        }
        __syncthreads();
#pragma unroll
        for (int kk = 0; kk < KC; kk += 8) {
            wmma::fragment<wmma::matrix_a, 16, 16, 8, wmma::precision::tf32,
                           wmma::row_major> a;
            wmma::fragment<wmma::matrix_b, 16, 16, 8, wmma::precision::tf32,
                           wmma::col_major> b;
            wmma::load_matrix_sync(a, &As[wn * 16][kk], 36);
            wmma::load_matrix_sync(b, &Bs[wm * 16][kk], 36);
#pragma unroll
            for (int i = 0; i < a.num_elements; i++)
                a.x[i] = wmma::__float_to_tf32(a.x[i]);
#pragma unroll
            for (int i = 0; i < b.num_elements; i++)
                b.x[i] = wmma::__float_to_tf32(b.x[i]);
            wmma::mma_sync(c, a, b, c);
        }
        __syncthreads();
    }
    wmma::store_matrix_sync(&g_Ct[(n0 + wn * 16) * DEm + m0 + wm * 16], c,
                            DEm, wmma::mem_row_major);
    __syncthreads();

    // fused stats: per-m partial sum/sumsq over this block's 64 n values
    __shared__ float sS[4][64];
    __shared__ float sQ[4][64];
    float s = 0.f, q = 0.f;
    int ml = tid & 63, grp = (tid >> 6) & 3;
    if (tid < 256) {
#pragma unroll
        for (int i = 0; i < 16; i++) {
            float x = g_Ct[(n0 + grp * 16 + i) * DEm + m0 + ml];
            s += x; q += x * x;
        }
        sS[grp][ml] = s;
        sQ[grp][ml] = q;
    }
    __syncthreads();
    if (tid < 64) {
        float ts = 0.f, tq = 0.f;
#pragma unroll
        for (int g2 = 0; g2 < 4; g2++) { ts += sS[g2][tid]; tq += sQ[g2][tid]; }
        atomicAdd(&g_sum [m0 + tid], ts);
        atomicAdd(&g_ssum[m0 + tid], tq);
    }
}

// K4: FUSED rd pass — one coalesced read of rd; sum(rd^2) partials; inline
// batchnorm from atomic stats; all dot-products for this bucket's entries.
__global__ void __launch_bounds__(256)
k_fused(const float* __restrict__ rd, const float* __restrict__ beta) {
    __shared__ float tile[DEm][33];     // [d][c], conflict-free both phases
    __shared__ float sMean[DEm], sFac[DEm], sBeta[DEm];
    __shared__ float red[8];
    int c0 = blockIdx.x * 32;
    int tx = threadIdx.x & 31;
    int ty = threadIdx.x >> 5;          // warp id 0..7
    float ss = 0.f;
#pragma unroll
    for (int d0 = 0; d0 < DEm; d0 += 8) {
        float v = __ldg(&rd[(size_t)(d0 + ty) * NDn + c0 + tx]);
        tile[d0 + ty][tx] = v;
        ss += v * v;
    }
    {
        int d = threadIdx.x;
        float s = g_sum[d], q = g_ssum[d];
        float mean = s * (1.0f / NB);
        float var  = fmaxf((q - (float)NB * mean * mean) * (1.0f / (NB - 1)), 0.f);
        sMean[d] = mean;
        sFac[d]  = rsqrtf(sqrtf(var));   // 1/sqrt(std), std ddof=1
        sBeta[d] = beta[d];
    }
    ss = warpSum(ss);
    if (tx == 0) red[ty] = ss;
    __syncthreads();
    if (threadIdx.x == 0) {
        float s = 0.f;
#pragma unroll
        for (int i = 0; i < 8; i++) s += red[i];
        g_regpart[blockIdx.x] = s;
    }
    int o0 = g_boff[blockIdx.x];
    int o1 = g_boff[blockIdx.x + 1];
    for (int e = o0 + ty; e < o1; e += 8) {
        int ent = g_bent[e];
        int c   = ent >> 16;
        int idx = ent & 0xFFFF;         // b*11 + v
        int b   = idx / 11;
        const float* crow = &g_Ct[b * DEm];
        float acc = 0.f;
#pragma unroll
        for (int i = 0; i < 8; i++) {
            int d = tx + i * 32;
            float tv = fminf(fmaxf((crow[d] - sMean[d]) * sFac[d] + sBeta[d],
                                   -1.f), 1.f);
            acc += tv * tile[d][c];
        }
        acc = warpSum(acc);
        if (tx == 0) g_dots[idx] = acc;
    }
}

// K5: merged loss + final reduce (threadfence-reduction; 32 blocks)
__global__ void __launch_bounds__(256)
k_tail(const float* __restrict__ proj, float* __restrict__ out) {
    int t = threadIdx.x, blk = blockIdx.x;
    double a = 0.0, r = 0.0;
    // loss for this block's 128 batches
    if (t < 128) {
        int b = blk * 128 + t;
        const float* d = &g_dots[b * 11];
        float lp = 10.f * fminf(log_sig(d[0]), -1.0005003e-3f);   // log(0.999)
        float ns = 0.f;
#pragma unroll
        for (int z = 0; z < NZ; z++)
            ns += fmaxf(log_sig(-d[1 + z]), -4.60517019f);        // log(0.01)
        a = (double)(0.55f * (lp + ns));                          // (Z+1)/(2Z)
    }
    // slice of sum(rd^2) partials
    {
        int i0 = blk * RSLICE;
        int i1 = min(i0 + RSLICE, NBKT);
        for (int i = i0 + t; i < i1; i += 256) r += (double)g_regpart[i];
    }
    // slice of sum(proj^2)
    {
        float ps = 0.f;
        int i0 = blk * PSLICE;
        for (int i = i0 + t; i < i0 + PSLICE; i += 256) {
            float v = proj[i];
            ps += v * v;
        }
        r += (double)ps;
    }
    __shared__ double sa[256], sr[256];
    sa[t] = a; sr[t] = r;
    __syncthreads();
    for (int o = 128; o; o >>= 1) {
        if (t < o) { sa[t] += sa[t + o]; sr[t] += sr[t + o]; }
        __syncthreads();
    }
    if (t == 0) {
        atomicAdd(&g_accA, sa[0]);
        atomicAdd(&g_accR, sr[0]);
        __threadfence();
        int tk = atomicAdd(&g_ticket, 1);
        if (tk == TAILB - 1) {
            __threadfence();
            double fa = g_accA, fr = g_accR;
            out[0] = (float)(fa / (double)NB + (0.01 / (2.0 * NB)) * fr);
        }
    }
}

// ---------------------------------------------------------------------------
static cudaStream_t g_s2;
static cudaEvent_t  g_e1, g_e2;
namespace {
struct _Init {
    _Init() {
        cudaStreamCreateWithFlags(&g_s2, cudaStreamNonBlocking);
        cudaEventCreateWithFlags(&g_e1, cudaEventDisableTiming);
        cudaEventCreateWithFlags(&g_e2, cudaEventDisableTiming);
    }
} _init;
}

extern "C" void kernel_launch(void* const* d_in, const int* in_sizes, int n_in,
                              void* d_out, int out_size) {
    const float* rv       = (const float*)d_in[0];
    const float* rd       = (const float*)d_in[1];
    const float* proj     = (const float*)d_in[2];
    const float* beta     = (const float*)d_in[3];
    const int*   word_ids = (const int*)d_in[4];
    const int*   doc_ids  = (const int*)d_in[5];
    const int*   neg_ids  = (const int*)d_in[6];

    // Side stream: CSR bucket build over doc/neg ids, overlapped with trv.
    cudaEventRecord(g_e1, 0);
    cudaStreamWaitEvent(g_s2, g_e1, 0);
    k_bzero <<<(NBKT + 255) / 256, 256, 0, g_s2>>>();
    k_bcount<<<(NENT + 255) / 256, 256, 0, g_s2>>>(doc_ids, neg_ids);
    k_bscan <<<1, 1024, 0, g_s2>>>();
    k_bfill <<<(NENT + 255) / 256, 256, 0, g_s2>>>(doc_ids, neg_ids);
    cudaEventRecord(g_e2, g_s2);

    // Main chain: 5 kernels
    k_trv   <<<dim3((NV + 31) / 32, WE2 / 64), 256>>>(rv);
    k_gather<<<NB, 256>>>(word_ids);
    k_gemm  <<<dim3(NB / 64, DEm / 64), 512>>>(proj);
    cudaStreamWaitEvent(0, g_e2, 0);   // join: fused needs buckets
    k_fused <<<NBKT, 256>>>(rd, beta);
    k_tail  <<<TAILB, 256>>>(proj, (float*)d_out);
}

// round 17
// speedup vs baseline: 1.2802x; 1.0206x over previous
#include <cuda_runtime.h>
#include <cuda_fp16.h>
#include <mma.h>
#include <math.h>

using namespace nvcuda;

// Problem constants
#define WE   300      // word embedding dim
#define WE2  320      // padded (fp16 staging) word dim
#define WEP  320      // padded gNT stride (mult of 32 for k-chunking)
#define KC   32       // GEMM k-chunk
#define DEm  256      // doc embedding dim
#define NV   50000    // vocab
#define NDn  100000   // num docs
#define NB   4096     // batch
#define NGw  10       // words per bag
#define NZ   10       // negatives
#define NENT (NB * 11)      // 45056 (b, slot) -> doc entries
#define NBKT (NDn / 32)     // 3125 doc buckets (32 cols each)
#define TAILB 32            // k_tail blocks
#define RSLICE ((NBKT + TAILB - 1) / TAILB)     // 98
#define PSLICE ((WE * DEm) / TAILB)             // 2400

// ---------------- scratch (device globals; no allocation) ----------------
__device__ __align__(16) __half g_rvT16[(size_t)NV * WE2];  // 32 MB fp16 staging
__device__ __align__(16) float g_gNT[NB * WEP];             // 4096 x 320 (pad=0)
__device__ __align__(16) float g_Ct[NB * DEm];              // t_pre^T: 4096 x 256
__device__ int   g_bcnt[NBKT];
__device__ int   g_boff[NBKT + 1];
__device__ int   g_bcur[NBKT];
__device__ int   g_bent[NENT];
__device__ float g_dots[NENT];
__device__ float g_sum [DEm];      // atomic stats accumulators
__device__ float g_ssum[DEm];
__device__ float g_regpart[NBKT];
__device__ double g_accA;          // loss accumulator (double atomics)
__device__ double g_accR;          // regularizer accumulator
__device__ int    g_ticket;

__device__ __forceinline__ float warpSum(float v) {
#pragma unroll
    for (int o = 16; o; o >>= 1) v += __shfl_down_sync(0xffffffffu, v, o);
    return v;
}
__device__ __forceinline__ float log_sig(float x) {
    return (x >= 0.f) ? -log1pf(expf(-x)) : x - log1pf(expf(x));
}

// ================= CSR bucket build (side stream; ids only) ================
__global__ void __launch_bounds__(256) k_bzero() {
    int i = blockIdx.x * 256 + threadIdx.x;
    if (i < NBKT) g_bcnt[i] = 0;
}
__global__ void __launch_bounds__(256)
k_bcount(const int* __restrict__ doc_ids, const int* __restrict__ neg_ids) {
    int i = blockIdx.x * 256 + threadIdx.x;
    if (i >= NENT) return;
    int doc = (i < NB) ? doc_ids[i] : neg_ids[i - NB];
    atomicAdd(&g_bcnt[doc >> 5], 1);
}
__global__ void __launch_bounds__(1024) k_bscan() {
    const int T = 1024, CH = (NBKT + T - 1) / T;   // 4
    __shared__ int s[T];
    int t = threadIdx.x;
    int base = t * CH;
    int sum = 0;
#pragma unroll 1
    for (int i = 0; i < CH; i++) {
        int v = base + i;
        if (v < NBKT) sum += g_bcnt[v];
    }
    s[t] = sum;
    __syncthreads();
    for (int o = 1; o < T; o <<= 1) {
        int x = (t >= o) ? s[t - o] : 0;
        __syncthreads();
        s[t] += x;
        __syncthreads();
    }
    int run = s[t] - sum;
#pragma unroll 1
    for (int i = 0; i < CH; i++) {
        int v = base + i;
        if (v < NBKT) {
            g_boff[v] = run;
            g_bcur[v] = run;
            run += g_bcnt[v];
        }
    }
    if (t == T - 1) g_boff[NBKT] = s[T - 1];
}
__global__ void __launch_bounds__(256)
k_bfill(const int* __restrict__ doc_ids, const int* __restrict__ neg_ids) {
    int i = blockIdx.x * 256 + threadIdx.x;
    if (i >= NENT) return;
    int b, v, doc;
    if (i < NB) { b = i; v = 0; doc = doc_ids[i]; }
    else {
        int j = i - NB;
        b = j / NZ; v = 1 + (j % NZ); doc = neg_ids[j];
    }
    int pos = atomicAdd(&g_bcur[doc >> 5], 1);
    g_bent[pos] = ((doc & 31) << 16) | (b * 11 + v);
}

// ================= main chain ==============================================
// K1: transpose rv (300 x 50000) -> fp16 rvT16 (50000 x 320, zero-padded).
__global__ void __launch_bounds__(256) k_trv(const float* __restrict__ rv) {
    __shared__ float t[64][33];
    int x0 = blockIdx.x * 32;      // v base
    int y0 = blockIdx.y * 64;      // k base
    int tx = threadIdx.x & 31, ty = threadIdx.x >> 5;   // 32 x 8
#pragma unroll
    for (int j = 0; j < 64; j += 8) {
        int k = y0 + ty + j, v = x0 + tx;
        t[ty + j][tx] = (k < WE && v < NV) ? rv[(size_t)k * NV + v] : 0.f;
    }
    __syncthreads();
#pragma unroll
    for (int j = 0; j < 32; j += 8) {
        int v = x0 + ty + j;
        if (v < NV) {
            __half2 h = __halves2half2(__float2half(t[2 * tx][ty + j]),
                                       __float2half(t[2 * tx + 1][ty + j]));
            *(__half2*)&g_rvT16[(size_t)v * WE2 + y0 + 2 * tx] = h;
        }
    }
}

// K2: gather — TWO bags per 320-thread block (threads r*160+i, bag r).
// Blocks 0/1 zero the stats accumulators; block 2 zeros tail accs/ticket.
__global__ void __launch_bounds__(320) k_gather(const int* __restrict__ word_ids) {
    int tid = threadIdx.x;                 // 320
    int r   = (tid >= 160) ? 1 : 0;        // bag within block
    int i   = tid - r * 160;               // 0..159
    int b   = blockIdx.x * 2 + r;
    if (blockIdx.x == 0 && tid < DEm) g_sum[tid]  = 0.f;
    if (blockIdx.x == 1 && tid < DEm) g_ssum[tid] = 0.f;
    if (blockIdx.x == 2 && tid == 0) { g_accA = 0.0; g_accR = 0.0; g_ticket = 0; }
    __shared__ int   wid[2 * NGw];
    __shared__ float red[10];              // 5 warps per bag
    __shared__ float rinvS[2];
    if (tid < 2 * NGw) wid[tid] = word_ids[blockIdx.x * 2 * NGw + tid];
    __syncthreads();
    float gx = 0.f, gy = 0.f;
    {
        const int* w = &wid[r * NGw];
#pragma unroll
        for (int j = 0; j < NGw; j++) {
            __half2 h = *(const __half2*)&g_rvT16[(size_t)w[j] * WE2 + 2 * i];
            float2 f = __half22float2(h);
            gx += f.x; gy += f.y;
        }
        gx *= 0.1f; gy *= 0.1f;
    }
    float s = warpSum(gx * gx + gy * gy);
    if ((tid & 31) == 0) red[tid >> 5] = s;   // warps 0-4 bag0, 5-9 bag1
    __syncthreads();
    if (i == 0) {                             // one thread per bag
        float t = 0.f;
#pragma unroll
        for (int w2 = 0; w2 < 5; w2++) t += red[r * 5 + w2];
        rinvS[r] = rsqrtf(t);
    }
    __syncthreads();
    float rinv = rinvS[r];
    *(float2*)&g_gNT[b * WEP + 2 * i] = make_float2(gx * rinv, gy * rinv);
}

// K3: tf32 tensor-core GEMM with SMEM-staged tiles (R14, unchanged).
__global__ void __launch_bounds__(512) k_gemm(const float* __restrict__ proj) {
    __shared__ float As[64][36];    // [n][k] chunk
    __shared__ float Bs[64][36];    // [m][k] chunk == B(k,m) col-major
    int tid  = threadIdx.x;
    int warp = tid >> 5;
    int wn = warp >> 2, wm = warp & 3;
    int n0 = blockIdx.x * 64, m0 = blockIdx.y * 64;

    wmma::fragment<wmma::accumulator, 16, 16, 8, float> c;
    wmma::fill_fragment(c, 0.f);

#pragma unroll 1
    for (int k0 = 0; k0 < WEP; k0 += KC) {      // 10 chunks
        {
            int row = tid >> 3, q = tid & 7;
            *(float4*)&As[row][q * 4] =
                *(const float4*)&g_gNT[(n0 + row) * WEP + k0 + q * 4];
        }
        {
#pragma unroll
            for (int i = tid; i < 64 * KC; i += 512) {
                int m = i >> 5, k = i & 31;
                int kk = k0 + k;
                Bs[m][k] = (kk < WE) ? proj[(size_t)(m0 + m) * WE + kk] : 0.f;
            }
        }
        __syncthreads();
#pragma unroll
        for (int kk = 0; kk < KC; kk += 8) {
            wmma::fragment<wmma::matrix_a, 16, 16, 8, wmma::precision::tf32,
                           wmma::row_major> a;
            wmma::fragment<wmma::matrix_b, 16, 16, 8, wmma::precision::tf32,
                           wmma::col_major> b;
            wmma::load_matrix_sync(a, &As[wn * 16][kk], 36);
            wmma::load_matrix_sync(b, &Bs[wm * 16][kk], 36);
#pragma unroll
            for (int i = 0; i < a.num_elements; i++)
                a.x[i] = wmma::__float_to_tf32(a.x[i]);
#pragma unroll
            for (int i = 0; i < b.num_elements; i++)
                b.x[i] = wmma::__float_to_tf32(b.x[i]);
            wmma::mma_sync(c, a, b, c);
        }
        __syncthreads();
    }
    wmma::store_matrix_sync(&g_Ct[(n0 + wn * 16) * DEm + m0 + wm * 16], c,
                            DEm, wmma::mem_row_major);
    __syncthreads();

    // fused stats: per-m partial sum/sumsq over this block's 64 n values
    __shared__ float sS[4][64];
    __shared__ float sQ[4][64];
    float s = 0.f, q = 0.f;
    int ml = tid & 63, grp = (tid >> 6) & 3;
    if (tid < 256) {
#pragma unroll
        for (int i = 0; i < 16; i++) {
            float x = g_Ct[(n0 + grp * 16 + i) * DEm + m0 + ml];
            s += x; q += x * x;
        }
        sS[grp][ml] = s;
        sQ[grp][ml] = q;
    }
    __syncthreads();
    if (tid < 64) {
        float ts = 0.f, tq = 0.f;
#pragma unroll
        for (int g2 = 0; g2 < 4; g2++) { ts += sS[g2][tid]; tq += sQ[g2][tid]; }
        atomicAdd(&g_sum [m0 + tid], ts);
        atomicAdd(&g_ssum[m0 + tid], tq);
    }
}

// K4: FUSED rd pass — float4 coalesced read of rd (lane covers 4 cols, warp
// covers 4 rows/iter); sum(rd^2) partials; inline batchnorm; bucket dots.
__global__ void __launch_bounds__(256)
k_fused(const float* __restrict__ rd, const float* __restrict__ beta) {
    __shared__ float tile[DEm][33];     // [d][c], conflict-free both phases
    __shared__ float sMean[DEm], sFac[DEm], sBeta[DEm];
    __shared__ float red[8];
    int c0 = blockIdx.x * 32;
    int tx = threadIdx.x & 31;
    int ty = threadIdx.x >> 5;          // warp id 0..7
    int lr = tx >> 3;                   // row-within-4 (0..3)
    int lq = tx & 7;                    // float4 col group (0..7)
    float ss = 0.f;
#pragma unroll
    for (int d0 = 0; d0 < DEm; d0 += 32) {      // 8 iters, 4 rows per warp
        int d = d0 + ty * 4 + lr;
        float4 v = __ldg((const float4*)&rd[(size_t)d * NDn + c0 + lq * 4]);
        tile[d][lq * 4 + 0] = v.x;
        tile[d][lq * 4 + 1] = v.y;
        tile[d][lq * 4 + 2] = v.z;
        tile[d][lq * 4 + 3] = v.w;
        ss += v.x * v.x + v.y * v.y + v.z * v.z + v.w * v.w;
    }
    {
        int d = threadIdx.x;
        float s = g_sum[d], q = g_ssum[d];
        float mean = s * (1.0f / NB);
        float var  = fmaxf((q - (float)NB * mean * mean) * (1.0f / (NB - 1)), 0.f);
        sMean[d] = mean;
        sFac[d]  = rsqrtf(sqrtf(var));   // 1/sqrt(std), std ddof=1
        sBeta[d] = beta[d];
    }
    ss = warpSum(ss);
    if (tx == 0) red[ty] = ss;
    __syncthreads();
    if (threadIdx.x == 0) {
        float s = 0.f;
#pragma unroll
        for (int i = 0; i < 8; i++) s += red[i];
        g_regpart[blockIdx.x] = s;
    }
    int o0 = g_boff[blockIdx.x];
    int o1 = g_boff[blockIdx.x + 1];
    for (int e = o0 + ty; e < o1; e += 8) {
        int ent = g_bent[e];
        int c   = ent >> 16;
        int idx = ent & 0xFFFF;         // b*11 + v
        int b   = idx / 11;
        const float* crow = &g_Ct[b * DEm];
        float acc = 0.f;
#pragma unroll
        for (int i = 0; i < 8; i++) {
            int d = tx + i * 32;
            float tv = fminf(fmaxf((crow[d] - sMean[d]) * sFac[d] + sBeta[d],
                                   -1.f), 1.f);
            acc += tv * tile[d][c];
        }
        acc = warpSum(acc);
        if (tx == 0) g_dots[idx] = acc;
    }
}

// K5: merged loss + final reduce (threadfence-reduction; 32 blocks)
__global__ void __launch_bounds__(256)
k_tail(const float* __restrict__ proj, float* __restrict__ out) {
    int t = threadIdx.x, blk = blockIdx.x;
    double a = 0.0, r = 0.0;
    if (t < 128) {
        int b = blk * 128 + t;
        const float* d = &g_dots[b * 11];
        float lp = 10.f * fminf(log_sig(d[0]), -1.0005003e-3f);   // log(0.999)
        float ns = 0.f;
#pragma unroll
        for (int z = 0; z < NZ; z++)
            ns += fmaxf(log_sig(-d[1 + z]), -4.60517019f);        // log(0.01)
        a = (double)(0.55f * (lp + ns));                          // (Z+1)/(2Z)
    }
    {
        int i0 = blk * RSLICE;
        int i1 = min(i0 + RSLICE, NBKT);
        for (int i = i0 + t; i < i1; i += 256) r += (double)g_regpart[i];
    }
    {
        float ps = 0.f;
        int i0 = blk * PSLICE;
        for (int i = i0 + t; i < i0 + PSLICE; i += 256) {
            float v = proj[i];
            ps += v * v;
        }
        r += (double)ps;
    }
    __shared__ double sa[256], sr[256];
    sa[t] = a; sr[t] = r;
    __syncthreads();
    for (int o = 128; o; o >>= 1) {
        if (t < o) { sa[t] += sa[t + o]; sr[t] += sr[t + o]; }
        __syncthreads();
    }
    if (t == 0) {
        atomicAdd(&g_accA, sa[0]);
        atomicAdd(&g_accR, sr[0]);
        __threadfence();
        int tk = atomicAdd(&g_ticket, 1);
        if (tk == TAILB - 1) {
            __threadfence();
            double fa = g_accA, fr = g_accR;
            out[0] = (float)(fa / (double)NB + (0.01 / (2.0 * NB)) * fr);
        }
    }
}

// ---------------------------------------------------------------------------
static cudaStream_t g_s2;
static cudaEvent_t  g_e1, g_e2;
namespace {
struct _Init {
    _Init() {
        cudaStreamCreateWithFlags(&g_s2, cudaStreamNonBlocking);
        cudaEventCreateWithFlags(&g_e1, cudaEventDisableTiming);
        cudaEventCreateWithFlags(&g_e2, cudaEventDisableTiming);
    }
} _init;
}

extern "C" void kernel_launch(void* const* d_in, const int* in_sizes, int n_in,
                              void* d_out, int out_size) {
    const float* rv       = (const float*)d_in[0];
    const float* rd       = (const float*)d_in[1];
    const float* proj     = (const float*)d_in[2];
    const float* beta     = (const float*)d_in[3];
    const int*   word_ids = (const int*)d_in[4];
    const int*   doc_ids  = (const int*)d_in[5];
    const int*   neg_ids  = (const int*)d_in[6];

    // Side stream: CSR bucket build over doc/neg ids, overlapped with trv.
    cudaEventRecord(g_e1, 0);
    cudaStreamWaitEvent(g_s2, g_e1, 0);
    k_bzero <<<(NBKT + 255) / 256, 256, 0, g_s2>>>();
    k_bcount<<<(NENT + 255) / 256, 256, 0, g_s2>>>(doc_ids, neg_ids);
    k_bscan <<<1, 1024, 0, g_s2>>>();
    k_bfill <<<(NENT + 255) / 256, 256, 0, g_s2>>>(doc_ids, neg_ids);
    cudaEventRecord(g_e2, g_s2);

    // Main chain: 5 kernels
    k_trv   <<<dim3((NV + 31) / 32, WE2 / 64), 256>>>(rv);
    k_gather<<<NB / 2, 320>>>(word_ids);
    k_gemm  <<<dim3(NB / 64, DEm / 64), 512>>>(proj);
    cudaStreamWaitEvent(0, g_e2, 0);   // join: fused needs buckets
    k_fused <<<NBKT, 256>>>(rd, beta);
    k_tail  <<<TAILB, 256>>>(proj, (float*)d_out);
}